// round 9
// baseline (speedup 1.0000x reference)
#include <cuda_runtime.h>

#define HW 262144      // 512*512
#define W  512

// cos(k*pi/16)
#define C1f 0.98078528040323044913f
#define C2f 0.92387953251128675613f
#define C3f 0.83146961230254523708f
#define C4f 0.70710678118654752440f
#define C5f 0.55557023301960222474f
#define C6f 0.38268343236508977173f
#define C7f 0.19509032201612826785f

// o[u] = sum_x a[x] * cos((2x+1)u pi/16)
__device__ __forceinline__ void dct8(const float* a, float* o) {
    float s0 = a[0] + a[7], s1 = a[1] + a[6];
    float s2 = a[2] + a[5], s3 = a[3] + a[4];
    float d0 = a[0] - a[7], d1 = a[1] - a[6];
    float d2 = a[2] - a[5], d3 = a[3] - a[4];
    float f0 = s0 + s3, f1 = s1 + s2;
    float e0 = s0 - s3, e1 = s1 - s2;
    o[0] = f0 + f1;
    o[4] = (f0 - f1) * C4f;
    o[2] = fmaf(e0, C2f,  e1 * C6f);
    o[6] = fmaf(e0, C6f, -e1 * C2f);
    o[1] = fmaf(d0, C1f, fmaf(d1,  C3f, fmaf(d2,  C5f,  d3 * C7f)));
    o[3] = fmaf(d0, C3f, fmaf(d1, -C7f, fmaf(d2, -C1f, -d3 * C5f)));
    o[5] = fmaf(d0, C5f, fmaf(d1, -C1f, fmaf(d2,  C7f,  d3 * C3f)));
    o[7] = fmaf(d0, C7f, fmaf(d1, -C5f, fmaf(d2,  C3f, -d3 * C1f)));
}

// o[x] = sum_u a[u] * cos((2x+1)u pi/16)
__device__ __forceinline__ void idct8(const float* a, float* o) {
    float E0 = fmaf(a[2],  C2f, fmaf(a[4],  C4f, fmaf(a[6],  C6f, a[0])));
    float E1 = fmaf(a[2],  C6f, fmaf(a[4], -C4f, fmaf(a[6], -C2f, a[0])));
    float E2 = fmaf(a[2], -C6f, fmaf(a[4], -C4f, fmaf(a[6],  C2f, a[0])));
    float E3 = fmaf(a[2], -C2f, fmaf(a[4],  C4f, fmaf(a[6], -C6f, a[0])));
    float O0 = fmaf(a[1],  C1f, fmaf(a[3],  C3f, fmaf(a[5],  C5f,  a[7] * C7f)));
    float O1 = fmaf(a[1],  C3f, fmaf(a[3], -C7f, fmaf(a[5], -C1f, -a[7] * C5f)));
    float O2 = fmaf(a[1],  C5f, fmaf(a[3], -C1f, fmaf(a[5],  C7f,  a[7] * C3f)));
    float O3 = fmaf(a[1],  C7f, fmaf(a[3], -C5f, fmaf(a[5],  C3f, -a[7] * C1f)));
    o[0] = E0 + O0;  o[7] = E0 - O0;
    o[1] = E1 + O1;  o[6] = E1 - O1;
    o[2] = E2 + O2;  o[5] = E2 - O2;
    o[3] = E3 + O3;  o[4] = E3 - O3;
}

// JPEG chain on one block row, scratch-based transpose (stride 12, warp-local).
// a[8] in/out (centered values). rs = &sRS[ti][2*r], pairs at stride 16 floats.
__device__ __forceinline__ void jpeg_chain(float* a, float* tg, int r,
                                           const float* rs) {
    float o[8];
    dct8(a, o);                                          // row DCT
    *(float4*)&tg[r * 12]     = make_float4(o[0], o[1], o[2], o[3]);
    *(float4*)&tg[r * 12 + 4] = make_float4(o[4], o[5], o[6], o[7]);
    __syncwarp();
    #pragma unroll
    for (int x = 0; x < 8; x++) a[x] = tg[x * 12 + r];   // column v = r
    dct8(a, o);                                          // o[u] = D[u][v]
    #pragma unroll
    for (int u = 0; u < 8; u++) {
        float2 RS = *(const float2*)&rs[16 * u];
        float tq = o[u] * RS.x;
        float rq = rintf(tq);                            // round-half-even
        float dq = tq - rq;
        a[u] = fmaf(dq * dq, dq, rq) * RS.y;
    }
    idct8(a, o);                                         // recon along column
    #pragma unroll
    for (int x = 0; x < 8; x++) tg[x * 12 + r] = o[x];
    __syncwarp();
    float4 w0 = *(const float4*)&tg[r * 12];
    float4 w1 = *(const float4*)&tg[r * 12 + 4];
    float t[8] = {w0.x, w0.y, w0.z, w0.w, w1.x, w1.y, w1.z, w1.w};
    idct8(t, a);                                         // final spatial row
}

__global__ __launch_bounds__(256, 6)
void diffjpeg_kernel(const float* __restrict__ img,
                     const float* __restrict__ ytab,
                     const float* __restrict__ ctab,
                     float* __restrict__ out)
{
    // chroma planes: 16 rows x 32 cols, stride 36
    __shared__ float sCb[16 * 36];
    __shared__ float sCr[16 * 36];
    // transpose scratch: 32 groups (warp*4 + seg_lo), row stride 12, group stride 104
    __shared__ float sT[32 * 104];
    // interleaved quant tables: [2i]=0.25*aa/(0.4*tab), [2i+1]=0.25*aa*0.4*tab
    __shared__ float sRS[2][128];

    const int tid = threadIdx.x;

    if (tid < 128) {
        int ti = tid >> 6, i = tid & 63;
        int u = i >> 3, v = i & 7;
        float aa = (u ? 1.0f : C4f) * (v ? 1.0f : C4f);
        float tq = (ti ? ctab[i] : ytab[i]) * 0.4f;
        sRS[ti][2 * i]     = 0.25f * aa / tq;
        sRS[ti][2 * i + 1] = 0.25f * aa * tq;
    }

    // ---------------- mapping: thread owns one Y block row -----------------
    // a = band (0..3), r = row in block, seg = block col (0..7)
    const int a      = tid >> 6;
    const int seg_hi = (tid >> 5) & 1;
    const int r      = (tid >> 2) & 7;
    const int seg_lo = tid & 3;
    const int seg    = seg_hi * 4 + seg_lo;
    const int wrp    = tid >> 5;
    float* const tg  = &sT[(wrp * 4 + seg_lo) * 104];

    const int tile = blockIdx.x;
    const int bimg = tile >> 7;            // 128 tiles per image
    const int t    = tile & 127;           // 16 x 8 tiles of 32x64
    const int grow = (t >> 3) * 32 + a * 8 + r;
    const int gcol = (t & 7) * 64 + seg * 8;

    // ---------------- front end: load 8 px, color convert, pool chroma -----
    const float* p = img + (size_t)bimg * 3 * HW + grow * W + gcol;
    float4 r0 = *(const float4*)(p);
    float4 r1 = *(const float4*)(p + 4);
    float4 g0 = *(const float4*)(p + HW);
    float4 g1 = *(const float4*)(p + HW + 4);
    float4 b0 = *(const float4*)(p + 2 * HW);
    float4 b1 = *(const float4*)(p + 2 * HW + 4);

    float R[8]  = {r0.x, r0.y, r0.z, r0.w, r1.x, r1.y, r1.z, r1.w};
    float G[8]  = {g0.x, g0.y, g0.z, g0.w, g1.x, g1.y, g1.z, g1.w};
    float Bc[8] = {b0.x, b0.y, b0.z, b0.w, b1.x, b1.y, b1.z, b1.w};

    float y[8];
    float cbh[4], crh[4];
    #pragma unroll
    for (int j2 = 0; j2 < 4; j2++) {
        int j = 2 * j2;
        // coeffs pre-multiplied by 255; Y centered (-128); chroma centered
        y[j]     = fmaf(R[j],   76.245f, fmaf(G[j],   149.685f, fmaf(Bc[j],   29.07f, -128.0f)));
        y[j + 1] = fmaf(R[j+1], 76.245f, fmaf(G[j+1], 149.685f, fmaf(Bc[j+1], 29.07f, -128.0f)));
        float cb0 = fmaf(R[j],   -43.02768f, fmaf(G[j],   -84.47232f,  Bc[j]   * 127.5f));
        float cb1 = fmaf(R[j+1], -43.02768f, fmaf(G[j+1], -84.47232f,  Bc[j+1] * 127.5f));
        float cr0 = fmaf(R[j],   127.5f,     fmaf(G[j],   -106.76544f, Bc[j]   * -20.73456f));
        float cr1 = fmaf(R[j+1], 127.5f,     fmaf(G[j+1], -106.76544f, Bc[j+1] * -20.73456f));
        cbh[j2] = cb0 + cb1;
        crh[j2] = cr0 + cr1;
    }
    // vertical partner: row r^1 lives at lane^4
    #pragma unroll
    for (int j2 = 0; j2 < 4; j2++) {
        cbh[j2] += __shfl_xor_sync(0xffffffffu, cbh[j2], 4);
        crh[j2] += __shfl_xor_sync(0xffffffffu, crh[j2], 4);
    }
    if (!(r & 1)) {
        int ci = (a * 4 + (r >> 1)) * 36 + seg * 4;
        *(float4*)&sCb[ci] = make_float4(0.25f * cbh[0], 0.25f * cbh[1],
                                         0.25f * cbh[2], 0.25f * cbh[3]);
        *(float4*)&sCr[ci] = make_float4(0.25f * crh[0], 0.25f * crh[1],
                                         0.25f * crh[2], 0.25f * crh[3]);
    }
    __syncthreads();   // chroma planes + quant tables ready

    // ---------------- Y chain: fully register-resident, warp-local sync ----
    jpeg_chain(y, tg, r, &sRS[0][2 * r]);

    // ---------------- chroma chains: warps 0-3, all lanes active -----------
    __syncwarp();      // this warp's Y scratch reads done before reuse
    if (wrp < 4) {
        int cblk = wrp * 4 + seg_lo;       // 0..15 (0-7 Cb, 8-15 Cr)
        float* plane = (cblk < 8) ? sCb : sCr;
        int pb = cblk & 7;
        int off = (((pb >> 2) * 8 + r) * 36) + (pb & 3) * 8;
        float c[8];
        float4 c0 = *(const float4*)&plane[off];
        float4 c1 = *(const float4*)&plane[off + 4];
        c[0] = c0.x; c[1] = c0.y; c[2] = c0.z; c[3] = c0.w;
        c[4] = c1.x; c[5] = c1.y; c[6] = c1.z; c[7] = c1.w;
        jpeg_chain(c, tg, r, &sRS[1][2 * r]);
        *(float4*)&plane[off]     = make_float4(c[0], c[1], c[2], c[3]);
        *(float4*)&plane[off + 4] = make_float4(c[4], c[5], c[6], c[7]);
    }
    __syncthreads();   // recon chroma visible

    // ---------------- back end: upsample, YCbCr->RGB, clip, store ----------
    const int ci = (a * 4 + (r >> 1)) * 36 + seg * 4;
    float4 cb4 = *(const float4*)&sCb[ci];
    float4 cr4 = *(const float4*)&sCr[ci];
    float cbp[4] = {cb4.x, cb4.y, cb4.z, cb4.w};
    float crp[4] = {cr4.x, cr4.y, cr4.z, cr4.w};

    float4 ov0, ov1, og0, og1, ob0, ob1;
    float* pro = &ov0.x; float* pro1 = &ov1.x;
    float* pgo = &og0.x; float* pgo1 = &og1.x;
    float* pbo = &ob0.x; float* pbo1 = &ob1.x;
    #pragma unroll
    for (int j = 0; j < 8; j++) {
        float yb = y[j] + 128.0f;
        float cc = cbp[j >> 1];
        float cv = crp[j >> 1];
        float ro = fmaf(cv,  1.402f,    yb);
        float go = fmaf(cv, -0.714136f, fmaf(cc, -0.344136f, yb));
        float bo = fmaf(cc,  1.772f,    yb);
        const float inv255 = 1.0f / 255.0f;
        ro = fminf(fmaxf(ro, 0.0f), 255.0f) * inv255;
        go = fminf(fmaxf(go, 0.0f), 255.0f) * inv255;
        bo = fminf(fmaxf(bo, 0.0f), 255.0f) * inv255;
        if (j < 4) { pro[j] = ro; pgo[j] = go; pbo[j] = bo; }
        else       { pro1[j-4] = ro; pgo1[j-4] = go; pbo1[j-4] = bo; }
    }
    float* q = out + (size_t)bimg * 3 * HW + grow * W + gcol;
    *(float4*)(q)              = ov0;
    *(float4*)(q + 4)          = ov1;
    *(float4*)(q + HW)         = og0;
    *(float4*)(q + HW + 4)     = og1;
    *(float4*)(q + 2 * HW)     = ob0;
    *(float4*)(q + 2 * HW + 4) = ob1;
}

extern "C" void kernel_launch(void* const* d_in, const int* in_sizes, int n_in,
                              void* d_out, int out_size)
{
    const float* img  = (const float*)d_in[0];
    const float* ytab = (const float*)d_in[1];
    const float* ctab = (const float*)d_in[2];
    float* out = (float*)d_out;

    // 32 images * (512/32)*(512/64) tiles = 4096 CTAs
    diffjpeg_kernel<<<4096, 256>>>(img, ytab, ctab, out);
}

// round 10
// speedup vs baseline: 1.1779x; 1.1779x over previous
#include <cuda_runtime.h>

#define HW 262144      // 512*512
#define W  512

// cos(k*pi/16)
#define C1f 0.98078528040323044913f
#define C2f 0.92387953251128675613f
#define C3f 0.83146961230254523708f
#define C4f 0.70710678118654752440f
#define C5f 0.55557023301960222474f
#define C6f 0.38268343236508977173f
#define C7f 0.19509032201612826785f

// o[u] = sum_x a[x] * cos((2x+1)u pi/16)
__device__ __forceinline__ void dct8(const float* a, float* o) {
    float s0 = a[0] + a[7], s1 = a[1] + a[6];
    float s2 = a[2] + a[5], s3 = a[3] + a[4];
    float d0 = a[0] - a[7], d1 = a[1] - a[6];
    float d2 = a[2] - a[5], d3 = a[3] - a[4];
    float f0 = s0 + s3, f1 = s1 + s2;
    float e0 = s0 - s3, e1 = s1 - s2;
    o[0] = f0 + f1;
    o[4] = (f0 - f1) * C4f;
    o[2] = fmaf(e0, C2f,  e1 * C6f);
    o[6] = fmaf(e0, C6f, -e1 * C2f);
    o[1] = fmaf(d0, C1f, fmaf(d1,  C3f, fmaf(d2,  C5f,  d3 * C7f)));
    o[3] = fmaf(d0, C3f, fmaf(d1, -C7f, fmaf(d2, -C1f, -d3 * C5f)));
    o[5] = fmaf(d0, C5f, fmaf(d1, -C1f, fmaf(d2,  C7f,  d3 * C3f)));
    o[7] = fmaf(d0, C7f, fmaf(d1, -C5f, fmaf(d2,  C3f, -d3 * C1f)));
}

// o[x] = sum_u a[u] * cos((2x+1)u pi/16)
__device__ __forceinline__ void idct8(const float* a, float* o) {
    float E0 = fmaf(a[2],  C2f, fmaf(a[4],  C4f, fmaf(a[6],  C6f, a[0])));
    float E1 = fmaf(a[2],  C6f, fmaf(a[4], -C4f, fmaf(a[6], -C2f, a[0])));
    float E2 = fmaf(a[2], -C6f, fmaf(a[4], -C4f, fmaf(a[6],  C2f, a[0])));
    float E3 = fmaf(a[2], -C2f, fmaf(a[4],  C4f, fmaf(a[6], -C6f, a[0])));
    float O0 = fmaf(a[1],  C1f, fmaf(a[3],  C3f, fmaf(a[5],  C5f,  a[7] * C7f)));
    float O1 = fmaf(a[1],  C3f, fmaf(a[3], -C7f, fmaf(a[5], -C1f, -a[7] * C5f)));
    float O2 = fmaf(a[1],  C5f, fmaf(a[3], -C1f, fmaf(a[5],  C7f,  a[7] * C3f)));
    float O3 = fmaf(a[1],  C7f, fmaf(a[3], -C5f, fmaf(a[5],  C3f, -a[7] * C1f)));
    o[0] = E0 + O0;  o[7] = E0 - O0;
    o[1] = E1 + O1;  o[6] = E1 - O1;
    o[2] = E2 + O2;  o[5] = E2 - O2;
    o[3] = E3 + O3;  o[4] = E3 - O3;
}

__global__ __launch_bounds__(256)
void diffjpeg_kernel(const float* __restrict__ img,
                     const float* __restrict__ ytab,
                     const float* __restrict__ ctab,
                     float* __restrict__ out)
{
    // pixel planes: strides multiple of 4 (16B-aligned rows) AND conflict-free
    __shared__ float sY [32 * 36];     // stride 36
    __shared__ float sCb[16 * 20];     // stride 20
    __shared__ float sCr[16 * 20];
    // transpose scratch: 24 groups, row stride 12 (16B-aligned), group stride 104
    __shared__ float sT [24 * 104];
    // interleaved quant tables: [2i] = 0.25*aa/(0.4*tab), [2i+1] = 0.25*aa*0.4*tab
    __shared__ float sRS[2][128];

    const int tid = threadIdx.x;

    if (tid < 128) {
        int ti = tid >> 6, i = tid & 63;
        int u = i >> 3, v = i & 7;
        float aa = (u ? 1.0f : C4f) * (v ? 1.0f : C4f);
        float tq = (ti ? ctab[i] : ytab[i]) * 0.4f;
        sRS[ti][2 * i]     = 0.25f * aa / tq;
        sRS[ti][2 * i + 1] = 0.25f * aa * tq;
    }

    // ---------------- front end: load RGB, YCbCr, 2x2 chroma pool ----------
    const int tile = blockIdx.x;
    const int bimg = tile >> 8;            // 256 tiles per image
    const int t    = tile & 255;
    const int ty   = tid >> 3;             // 0..31
    const int txq  = tid & 7;              // 0..7 (x in float4 units)
    const int grow = (t >> 4) * 32 + ty;
    const int gcol = (t & 15) * 32 + txq * 4;

    const float* p = img + (size_t)bimg * 3 * HW + grow * W + gcol;
    float4 r4 = *(const float4*)p;
    float4 g4 = *(const float4*)(p + HW);
    float4 b4 = *(const float4*)(p + 2 * HW);

    float rr[4] = {r4.x, r4.y, r4.z, r4.w};
    float gg[4] = {g4.x, g4.y, g4.z, g4.w};
    float bb[4] = {b4.x, b4.y, b4.z, b4.w};

    float yv[4], cbv[4], crv[4];
    #pragma unroll
    for (int j = 0; j < 4; j++) {
        // coefficients pre-multiplied by 255; Y centered (-128)
        yv [j] = fmaf(rr[j],  76.245f,   fmaf(gg[j],  149.685f,  fmaf(bb[j],  29.07f,    -128.0f)));
        cbv[j] = fmaf(rr[j], -43.02768f, fmaf(gg[j], -84.47232f,       bb[j] * 127.5f));
        crv[j] = fmaf(rr[j], 127.5f,     fmaf(gg[j], -106.76544f,     bb[j] * -20.73456f));
    }

    *(float4*)&sY[ty * 36 + txq * 4] = make_float4(yv[0], yv[1], yv[2], yv[3]);

    // horizontal pair sums in-thread, vertical partner via shfl (row ty^1 = tid^8)
    float cb0 = cbv[0] + cbv[1], cb1 = cbv[2] + cbv[3];
    float cr0 = crv[0] + crv[1], cr1 = crv[2] + crv[3];
    float cb0o = __shfl_xor_sync(0xffffffffu, cb0, 8);
    float cb1o = __shfl_xor_sync(0xffffffffu, cb1, 8);
    float cr0o = __shfl_xor_sync(0xffffffffu, cr0, 8);
    float cr1o = __shfl_xor_sync(0xffffffffu, cr1, 8);
    if (!(ty & 1)) {
        int ci = (ty >> 1) * 20 + txq * 2;
        *(float2*)&sCb[ci] = make_float2(0.25f * (cb0 + cb0o), 0.25f * (cb1 + cb1o));
        *(float2*)&sCr[ci] = make_float2(0.25f * (cr0 + cr0o), 0.25f * (cr1 + cr1o));
    }
    __syncthreads();

    // ---------------- transforms: groups warp-local ------------------------
    // blk = tid>>3: groups 0..23 live on warps 0..5 (4 groups per warp).
    // 0..15 = Y blocks (4x4), 16..19 = Cb, 20..23 = Cr. Warps 6,7 idle here.
    float* plane = sY;
    int poff = 0, ti = 0;
    const int blk = tid >> 3, r = tid & 7;
    const bool act = (tid < 192);
    if (act) {
        if (blk < 16) {
            plane = sY;  poff = ((blk >> 2) * 8 + r) * 36 + (blk & 3) * 8;  ti = 0;
        } else {
            int b = blk & 3;
            plane = (blk < 20) ? sCb : sCr;
            poff = (((b >> 1) * 8 + r) * 20) + (b & 1) * 8;  ti = 1;
        }
    }
    float* const trow = &sT[blk * 104 + r * 12];   // 16B-aligned row base
    float* const tcol = &sT[blk * 104 + r];        // column base, v = r

    float a[8], o[8];

    if (act) {
        // stage 1: row DCT, vector plane read, vector row write
        float4 v0 = *(const float4*)&plane[poff];
        float4 v1 = *(const float4*)&plane[poff + 4];
        a[0] = v0.x; a[1] = v0.y; a[2] = v0.z; a[3] = v0.w;
        a[4] = v1.x; a[5] = v1.y; a[6] = v1.z; a[7] = v1.w;
        dct8(a, o);
        *(float4*)&trow[0] = make_float4(o[0], o[1], o[2], o[3]);
        *(float4*)&trow[4] = make_float4(o[4], o[5], o[6], o[7]);
        __syncwarp();      // groups are warp-local

        // stage 2+3: column DCT, quant/dequant (diff_round), column IDCT
        #pragma unroll
        for (int x = 0; x < 8; x++) a[x] = tcol[12 * x];
        dct8(a, o);
        const float* pT = &sRS[ti][2 * r];
        #pragma unroll
        for (int u = 0; u < 8; u++) {
            float2 rs = *(const float2*)&pT[16 * u];
            float tq = o[u] * rs.x;
            float rq = rintf(tq);            // round-half-even == jnp.round
            float dq = tq - rq;
            a[u] = fmaf(dq * dq, dq, rq) * rs.y;
        }
        idct8(a, o);                          // o[x] = recon column v
        #pragma unroll
        for (int x = 0; x < 8; x++) tcol[12 * x] = o[x];
        __syncwarp();

        // stage 4: row IDCT, vector row read, vector plane write (centered)
        float4 w0 = *(const float4*)&trow[0];
        float4 w1 = *(const float4*)&trow[4];
        a[0] = w0.x; a[1] = w0.y; a[2] = w0.z; a[3] = w0.w;
        a[4] = w1.x; a[5] = w1.y; a[6] = w1.z; a[7] = w1.w;
        idct8(a, o);
        *(float4*)&plane[poff]     = make_float4(o[0], o[1], o[2], o[3]);
        *(float4*)&plane[poff + 4] = make_float4(o[4], o[5], o[6], o[7]);
    }
    __syncthreads();

    // ---------------- back end: upsample, YCbCr->RGB, clip, store ----------
    float4 yq = *(const float4*)&sY[ty * 36 + txq * 4];
    const int ci = (ty >> 1) * 20 + txq * 2;
    float2 cbl = *(const float2*)&sCb[ci];
    float2 crl = *(const float2*)&sCr[ci];

    float yb[4] = {yq.x + 128.0f, yq.y + 128.0f, yq.z + 128.0f, yq.w + 128.0f};
    float cbp[4] = {cbl.x, cbl.x, cbl.y, cbl.y};
    float crp[4] = {crl.x, crl.x, crl.y, crl.y};

    float4 orv, ogv, obv;
    float* po_r = &orv.x;
    float* po_g = &ogv.x;
    float* po_b = &obv.x;
    #pragma unroll
    for (int j = 0; j < 4; j++) {
        float ro = fmaf(crp[j],  1.402f,    yb[j]);
        float go = fmaf(crp[j], -0.714136f, fmaf(cbp[j], -0.344136f, yb[j]));
        float bo = fmaf(cbp[j],  1.772f,    yb[j]);
        const float inv255 = 1.0f / 255.0f;
        po_r[j] = fminf(fmaxf(ro, 0.0f), 255.0f) * inv255;
        po_g[j] = fminf(fmaxf(go, 0.0f), 255.0f) * inv255;
        po_b[j] = fminf(fmaxf(bo, 0.0f), 255.0f) * inv255;
    }
    float* q = out + (size_t)bimg * 3 * HW + grow * W + gcol;
    *(float4*)q            = orv;
    *(float4*)(q + HW)     = ogv;
    *(float4*)(q + 2 * HW) = obv;
}

extern "C" void kernel_launch(void* const* d_in, const int* in_sizes, int n_in,
                              void* d_out, int out_size)
{
    const float* img  = (const float*)d_in[0];
    const float* ytab = (const float*)d_in[1];
    const float* ctab = (const float*)d_in[2];
    float* out = (float*)d_out;

    // 32 images * (512/32)^2 tiles = 8192 CTAs
    diffjpeg_kernel<<<8192, 256>>>(img, ytab, ctab, out);
}

// round 11
// speedup vs baseline: 1.2303x; 1.0445x over previous
#include <cuda_runtime.h>

#define HW 262144      // 512*512
#define W  512

// cos(k*pi/16)
#define C1f 0.98078528040323044913f
#define C2f 0.92387953251128675613f
#define C3f 0.83146961230254523708f
#define C4f 0.70710678118654752440f
#define C5f 0.55557023301960222474f
#define C6f 0.38268343236508977173f
#define C7f 0.19509032201612826785f

// o[u] = sum_x a[x] * cos((2x+1)u pi/16)
__device__ __forceinline__ void dct8(const float* a, float* o) {
    float s0 = a[0] + a[7], s1 = a[1] + a[6];
    float s2 = a[2] + a[5], s3 = a[3] + a[4];
    float d0 = a[0] - a[7], d1 = a[1] - a[6];
    float d2 = a[2] - a[5], d3 = a[3] - a[4];
    float f0 = s0 + s3, f1 = s1 + s2;
    float e0 = s0 - s3, e1 = s1 - s2;
    o[0] = f0 + f1;
    o[4] = (f0 - f1) * C4f;
    o[2] = fmaf(e0, C2f,  e1 * C6f);
    o[6] = fmaf(e0, C6f, -e1 * C2f);
    o[1] = fmaf(d0, C1f, fmaf(d1,  C3f, fmaf(d2,  C5f,  d3 * C7f)));
    o[3] = fmaf(d0, C3f, fmaf(d1, -C7f, fmaf(d2, -C1f, -d3 * C5f)));
    o[5] = fmaf(d0, C5f, fmaf(d1, -C1f, fmaf(d2,  C7f,  d3 * C3f)));
    o[7] = fmaf(d0, C7f, fmaf(d1, -C5f, fmaf(d2,  C3f, -d3 * C1f)));
}

// o[x] = sum_u a[u] * cos((2x+1)u pi/16)
__device__ __forceinline__ void idct8(const float* a, float* o) {
    float E0 = fmaf(a[2],  C2f, fmaf(a[4],  C4f, fmaf(a[6],  C6f, a[0])));
    float E1 = fmaf(a[2],  C6f, fmaf(a[4], -C4f, fmaf(a[6], -C2f, a[0])));
    float E2 = fmaf(a[2], -C6f, fmaf(a[4], -C4f, fmaf(a[6],  C2f, a[0])));
    float E3 = fmaf(a[2], -C2f, fmaf(a[4],  C4f, fmaf(a[6], -C6f, a[0])));
    float O0 = fmaf(a[1],  C1f, fmaf(a[3],  C3f, fmaf(a[5],  C5f,  a[7] * C7f)));
    float O1 = fmaf(a[1],  C3f, fmaf(a[3], -C7f, fmaf(a[5], -C1f, -a[7] * C5f)));
    float O2 = fmaf(a[1],  C5f, fmaf(a[3], -C1f, fmaf(a[5],  C7f,  a[7] * C3f)));
    float O3 = fmaf(a[1],  C7f, fmaf(a[3], -C5f, fmaf(a[5],  C3f, -a[7] * C1f)));
    o[0] = E0 + O0;  o[7] = E0 - O0;
    o[1] = E1 + O1;  o[6] = E1 - O1;
    o[2] = E2 + O2;  o[5] = E2 - O2;
    o[3] = E3 + O3;  o[4] = E3 - O3;
}

__global__ __launch_bounds__(256)
void diffjpeg_kernel(const float* __restrict__ img,
                     const float* __restrict__ ytab,
                     const float* __restrict__ ctab,
                     float* __restrict__ out)
{
    // pixel planes: strides multiple of 4 (16B-aligned rows) AND conflict-free
    __shared__ float sY [32 * 36];     // stride 36
    __shared__ float sCb[16 * 20];     // stride 20
    __shared__ float sCr[16 * 20];
    // transpose scratch: 24 groups, row stride 12 (16B-aligned), group stride 104
    __shared__ float sT [24 * 104];
    // interleaved quant tables: [2i] = 0.25*aa/(0.4*tab), [2i+1] = 0.25*aa*0.4*tab
    __shared__ float sRS[2][128];

    const int tid = threadIdx.x;

    // quant-table init on warps 6,7 (idle during transform phase)
    if (tid >= 192) {
        #pragma unroll
        for (int k = 0; k < 2; k++) {
            int idx = (tid - 192) + 64 * k;      // 0..127
            int ti = idx >> 6, i = idx & 63;
            int u = i >> 3, v = i & 7;
            float aa = (u ? 1.0f : C4f) * (v ? 1.0f : C4f);
            float tq = (ti ? ctab[i] : ytab[i]) * 0.4f;
            sRS[ti][2 * i]     = 0.25f * aa / tq;
            sRS[ti][2 * i + 1] = 0.25f * aa * tq;
        }
    }

    // ---------------- front end: load RGB, YCbCr, 2x2 chroma pool ----------
    const int tile = blockIdx.x;
    const int bimg = tile >> 8;            // 256 tiles per image
    const int t    = tile & 255;
    const int ty   = tid >> 3;             // 0..31
    const int txq  = tid & 7;              // 0..7 (x in float4 units)
    const int grow = (t >> 4) * 32 + ty;
    const int gcol = (t & 15) * 32 + txq * 4;

    const float* p = img + (size_t)bimg * 3 * HW + grow * W + gcol;
    float4 r4 = __ldcs((const float4*)p);
    float4 g4 = __ldcs((const float4*)(p + HW));
    float4 b4 = __ldcs((const float4*)(p + 2 * HW));

    float rr[4] = {r4.x, r4.y, r4.z, r4.w};
    float gg[4] = {g4.x, g4.y, g4.z, g4.w};
    float bb[4] = {b4.x, b4.y, b4.z, b4.w};

    float yv[4], cbv[4], crv[4];
    #pragma unroll
    for (int j = 0; j < 4; j++) {
        // coefficients pre-multiplied by 255; Y centered (-128)
        yv [j] = fmaf(rr[j],  76.245f,   fmaf(gg[j],  149.685f,  fmaf(bb[j],  29.07f,    -128.0f)));
        cbv[j] = fmaf(rr[j], -43.02768f, fmaf(gg[j], -84.47232f,       bb[j] * 127.5f));
        crv[j] = fmaf(rr[j], 127.5f,     fmaf(gg[j], -106.76544f,     bb[j] * -20.73456f));
    }

    *(float4*)&sY[ty * 36 + txq * 4] = make_float4(yv[0], yv[1], yv[2], yv[3]);

    // horizontal pair sums in-thread, vertical partner via shfl (row ty^1 = tid^8)
    float cb0 = cbv[0] + cbv[1], cb1 = cbv[2] + cbv[3];
    float cr0 = crv[0] + crv[1], cr1 = crv[2] + crv[3];
    float cb0o = __shfl_xor_sync(0xffffffffu, cb0, 8);
    float cb1o = __shfl_xor_sync(0xffffffffu, cb1, 8);
    float cr0o = __shfl_xor_sync(0xffffffffu, cr0, 8);
    float cr1o = __shfl_xor_sync(0xffffffffu, cr1, 8);
    if (!(ty & 1)) {
        int ci = (ty >> 1) * 20 + txq * 2;
        *(float2*)&sCb[ci] = make_float2(0.25f * (cb0 + cb0o), 0.25f * (cb1 + cb1o));
        *(float2*)&sCr[ci] = make_float2(0.25f * (cr0 + cr0o), 0.25f * (cr1 + cr1o));
    }
    __syncthreads();

    // ---------------- transforms: groups warp-local ------------------------
    // blk = tid>>3: groups 0..23 live on warps 0..5 (4 groups per warp).
    // 0..15 = Y blocks (4x4), 16..19 = Cb, 20..23 = Cr. Warps 6,7 idle here.
    float* plane = sY;
    int poff = 0, ti = 0;
    const int blk = tid >> 3, r = tid & 7;
    const bool act = (tid < 192);
    if (act) {
        if (blk < 16) {
            plane = sY;  poff = ((blk >> 2) * 8 + r) * 36 + (blk & 3) * 8;  ti = 0;
        } else {
            int b = blk & 3;
            plane = (blk < 20) ? sCb : sCr;
            poff = (((b >> 1) * 8 + r) * 20) + (b & 1) * 8;  ti = 1;
        }
    }
    float* const trow = &sT[blk * 104 + r * 12];   // 16B-aligned row base
    float* const tcol = &sT[blk * 104 + r];        // column base, v = r

    float a[8], o[8];

    if (act) {
        // stage 1: row DCT, vector plane read, vector row write
        float4 v0 = *(const float4*)&plane[poff];
        float4 v1 = *(const float4*)&plane[poff + 4];
        a[0] = v0.x; a[1] = v0.y; a[2] = v0.z; a[3] = v0.w;
        a[4] = v1.x; a[5] = v1.y; a[6] = v1.z; a[7] = v1.w;
        dct8(a, o);
        *(float4*)&trow[0] = make_float4(o[0], o[1], o[2], o[3]);
        *(float4*)&trow[4] = make_float4(o[4], o[5], o[6], o[7]);
        __syncwarp();      // groups are warp-local

        // stage 2+3: column DCT, quant/dequant (diff_round), column IDCT
        #pragma unroll
        for (int x = 0; x < 8; x++) a[x] = tcol[12 * x];
        dct8(a, o);
        const float* pT = &sRS[ti][2 * r];
        #pragma unroll
        for (int u = 0; u < 8; u++) {
            float2 rs = *(const float2*)&pT[16 * u];
            float tq = o[u] * rs.x;
            float rq = rintf(tq);            // round-half-even == jnp.round
            float dq = tq - rq;
            a[u] = fmaf(dq * dq, dq, rq) * rs.y;
        }
        idct8(a, o);                          // o[x] = recon column v
        #pragma unroll
        for (int x = 0; x < 8; x++) tcol[12 * x] = o[x];
        __syncwarp();

        // stage 4: row IDCT, vector row read, vector plane write (centered)
        float4 w0 = *(const float4*)&trow[0];
        float4 w1 = *(const float4*)&trow[4];
        a[0] = w0.x; a[1] = w0.y; a[2] = w0.z; a[3] = w0.w;
        a[4] = w1.x; a[5] = w1.y; a[6] = w1.z; a[7] = w1.w;
        idct8(a, o);
        *(float4*)&plane[poff]     = make_float4(o[0], o[1], o[2], o[3]);
        *(float4*)&plane[poff + 4] = make_float4(o[4], o[5], o[6], o[7]);
    }
    __syncthreads();

    // ---------------- back end: upsample, YCbCr->RGB, clip, store ----------
    // /255 folded into coefficients; clip in [0,1].
    const float KI  = 1.0f / 255.0f;           // y scale
    const float KO  = 128.0f / 255.0f;         // +128 then /255
    const float KCr = 1.402f / 255.0f;
    const float KG1 = -0.344136f / 255.0f;
    const float KG2 = -0.714136f / 255.0f;
    const float KCb = 1.772f / 255.0f;

    float4 yq = *(const float4*)&sY[ty * 36 + txq * 4];
    const int ci = (ty >> 1) * 20 + txq * 2;
    float2 cbl = *(const float2*)&sCb[ci];
    float2 crl = *(const float2*)&sCr[ci];

    float yb[4]  = {fmaf(yq.x, KI, KO), fmaf(yq.y, KI, KO),
                    fmaf(yq.z, KI, KO), fmaf(yq.w, KI, KO)};
    float cbp[4] = {cbl.x, cbl.x, cbl.y, cbl.y};
    float crp[4] = {crl.x, crl.x, crl.y, crl.y};

    float4 orv, ogv, obv;
    float* po_r = &orv.x;
    float* po_g = &ogv.x;
    float* po_b = &obv.x;
    #pragma unroll
    for (int j = 0; j < 4; j++) {
        float ro = fmaf(crp[j], KCr, yb[j]);
        float go = fmaf(crp[j], KG2, fmaf(cbp[j], KG1, yb[j]));
        float bo = fmaf(cbp[j], KCb, yb[j]);
        po_r[j] = fminf(fmaxf(ro, 0.0f), 1.0f);
        po_g[j] = fminf(fmaxf(go, 0.0f), 1.0f);
        po_b[j] = fminf(fmaxf(bo, 0.0f), 1.0f);
    }
    float* q = out + (size_t)bimg * 3 * HW + grow * W + gcol;
    __stcs((float4*)q,            orv);
    __stcs((float4*)(q + HW),     ogv);
    __stcs((float4*)(q + 2 * HW), obv);
}

extern "C" void kernel_launch(void* const* d_in, const int* in_sizes, int n_in,
                              void* d_out, int out_size)
{
    const float* img  = (const float*)d_in[0];
    const float* ytab = (const float*)d_in[1];
    const float* ctab = (const float*)d_in[2];
    float* out = (float*)d_out;

    // 32 images * (512/32)^2 tiles = 8192 CTAs
    diffjpeg_kernel<<<8192, 256>>>(img, ytab, ctab, out);
}